// round 1
// baseline (speedup 1.0000x reference)
#include <cuda_runtime.h>

#define B_N   32768
#define C_INN 14
#define NN    52      // nodes / conv channels
#define H1D   64
#define H2D   128
#define FDIM  (NN*H2D)  // 6656
#define EPSB  1e-5f
#define SPB   8       // samples per block in k1
#define KT    32      // k-tile in k3
#define TBM   64      // samples per block in k3

// ---------------- scratch (device globals; no allocations allowed) ----------
__device__ float d_W01[H2D * C_INN];                 // folded w1@w0  [128][14]
__device__ float d_b01[H2D];
__device__ float d_Y[(size_t)B_N * NN * H2D];        // 872 MB intermediate
__device__ float d_f[(size_t)B_N * H1D];             // fc1 output
__device__ float d_sum1[NN], d_sq1[NN];
__device__ float d_sum2[H1D], d_sq2[H1D];
__device__ float d_a1[NN], d_c1[NN];
__device__ float d_a2[H1D], d_c2[H1D];

// ---------------- tiny kernels ----------------------------------------------
__global__ void kinit() {
    int t = threadIdx.x;
    if (t < NN)  { d_sum1[t] = 0.f; d_sq1[t] = 0.f; }
    if (t < H1D) { d_sum2[t] = 0.f; d_sq2[t] = 0.f; }
}

// fold GAT+GCN weights: W01 = w1 @ w0  [128][14], b01 = w1@b0 + b1
__global__ void kprep(const float* __restrict__ w0, const float* __restrict__ b0,
                      const float* __restrict__ w1, const float* __restrict__ b1) {
    int l = threadIdx.x;           // 128 threads
    if (l >= H2D) return;
    float bb = b1[l];
    for (int m = 0; m < H1D; m++) bb = fmaf(w1[l*H1D + m], b0[m], bb);
    d_b01[l] = bb;
    for (int j = 0; j < C_INN; j++) {
        float s = 0.f;
        for (int m = 0; m < H1D; m++) s = fmaf(w1[l*H1D + m], w0[m*C_INN + j], s);
        d_W01[l*C_INN + j] = s;
    }
}

__global__ void k2(const float* __restrict__ g1, const float* __restrict__ be1) {
    int t = threadIdx.x;
    if (t < NN) {
        float inv = 1.f / ((float)B_N * (float)H2D);
        float mu  = d_sum1[t] * inv;
        float var = d_sq1[t] * inv - mu * mu;
        float a   = g1[t] * rsqrtf(var + EPSB);
        d_a1[t] = a; d_c1[t] = be1[t] - mu * a;
    }
}

__global__ void k4(const float* __restrict__ g2, const float* __restrict__ be2) {
    int t = threadIdx.x;
    if (t < H1D) {
        float inv = 1.f / (float)B_N;
        float mu  = d_sum2[t] * inv;
        float var = d_sq2[t] * inv - mu * mu;
        float a   = g2[t] * rsqrtf(var + EPSB);
        d_a2[t] = a; d_c2[t] = be2[t] - mu * a;
    }
}

// ---------------- K1: per-sample H = relu(X@W01^T+b01); Y = wc@H + bc -------
__global__ __launch_bounds__(256, 2)
void k1(const float* __restrict__ x, const float* __restrict__ wc,
        const float* __restrict__ bc) {
    __shared__ float wc_s[NN * NN];        // [o][c]  10816 B
    __shared__ float W01t_s[C_INN * H2D];  // [j][l]   7168 B
    __shared__ float b01_s[H2D];
    __shared__ float bc_s[NN];
    __shared__ float X_s[64 * C_INN];      // [node][j], rows 52..63 unused
    __shared__ float H_s[NN * H2D];        // [c][l]  26624 B

    const int t = threadIdx.x;

    for (int i = t; i < NN * NN; i += 256) wc_s[i] = wc[i];
    for (int i = t; i < H2D * C_INN; i += 256) {
        int l = i / C_INN, j = i - l * C_INN;
        W01t_s[j * H2D + l] = d_W01[i];
    }
    if (t < H2D) b01_s[t] = d_b01[t];
    if (t < NN)  bc_s[t]  = bc[t];

    const int tx = t & 15, ty = t >> 4;
    const int l0 = tx * 8;           // feature-column tile
    const int r0 = ty * 4;           // row tile (c for H stage, o for Y stage)

    float s_acc[4] = {0.f,0.f,0.f,0.f}, q_acc[4] = {0.f,0.f,0.f,0.f};

    const size_t base = (size_t)blockIdx.x * SPB;
    for (int sp = 0; sp < SPB; sp++) {
        const size_t b = base + sp;
        __syncthreads();  // previous sample's readers done
        // load X: x[b][j][n] -> X_s[n][j]
        const float* xb = x + b * (C_INN * NN);
        for (int i = t; i < C_INN * NN; i += 256) {
            int j = i / NN, n = i - j * NN;
            X_s[n * C_INN + j] = xb[i];
        }
        __syncthreads();

        // ---- H stage: H[c][l] = relu(sum_j X[c][j]*W01[l][j] + b01[l]) ----
        {
            float acc[4][8];
            float b01v[8];
            #pragma unroll
            for (int i = 0; i < 8; i++) b01v[i] = b01_s[l0 + i];
            #pragma unroll
            for (int a = 0; a < 4; a++)
                #pragma unroll
                for (int i = 0; i < 8; i++) acc[a][i] = b01v[i];
            #pragma unroll
            for (int j = 0; j < C_INN; j++) {
                float4 wA = *(const float4*)&W01t_s[j * H2D + l0];
                float4 wB = *(const float4*)&W01t_s[j * H2D + l0 + 4];
                float wv[8] = {wA.x,wA.y,wA.z,wA.w,wB.x,wB.y,wB.z,wB.w};
                #pragma unroll
                for (int a = 0; a < 4; a++) {
                    float xv = X_s[(r0 + a) * C_INN + j];
                    #pragma unroll
                    for (int i = 0; i < 8; i++) acc[a][i] = fmaf(xv, wv[i], acc[a][i]);
                }
            }
            #pragma unroll
            for (int a = 0; a < 4; a++) {
                int c = r0 + a;
                if (c < NN) {
                    float4 o0v, o1v;
                    o0v.x = fmaxf(acc[a][0], 0.f); o0v.y = fmaxf(acc[a][1], 0.f);
                    o0v.z = fmaxf(acc[a][2], 0.f); o0v.w = fmaxf(acc[a][3], 0.f);
                    o1v.x = fmaxf(acc[a][4], 0.f); o1v.y = fmaxf(acc[a][5], 0.f);
                    o1v.z = fmaxf(acc[a][6], 0.f); o1v.w = fmaxf(acc[a][7], 0.f);
                    *(float4*)&H_s[c * H2D + l0]     = o0v;
                    *(float4*)&H_s[c * H2D + l0 + 4] = o1v;
                }
            }
        }
        __syncthreads();

        // ---- Y stage: Y[o][l] = sum_c wc[o][c]*H[c][l] + bc[o] ----
        {
            float acc[4][8];
            const float* wrow[4];
            #pragma unroll
            for (int kk = 0; kk < 4; kk++) {
                int o = r0 + kk; if (o > NN - 1) o = NN - 1;  // clamp; discarded later
                wrow[kk] = &wc_s[o * NN];
                float bcv = bc_s[o];
                #pragma unroll
                for (int i = 0; i < 8; i++) acc[kk][i] = bcv;
            }
            #pragma unroll 4
            for (int c = 0; c < NN; c++) {
                float4 hA = *(const float4*)&H_s[c * H2D + l0];
                float4 hB = *(const float4*)&H_s[c * H2D + l0 + 4];
                float hv[8] = {hA.x,hA.y,hA.z,hA.w,hB.x,hB.y,hB.z,hB.w};
                #pragma unroll
                for (int kk = 0; kk < 4; kk++) {
                    float wv = wrow[kk][c];
                    #pragma unroll
                    for (int i = 0; i < 8; i++) acc[kk][i] = fmaf(wv, hv[i], acc[kk][i]);
                }
            }
            #pragma unroll
            for (int kk = 0; kk < 4; kk++) {
                int o = r0 + kk;
                if (o < NN) {
                    float* yp = d_Y + ((size_t)b * NN + o) * H2D + l0;
                    float4 o0v = {acc[kk][0],acc[kk][1],acc[kk][2],acc[kk][3]};
                    float4 o1v = {acc[kk][4],acc[kk][5],acc[kk][6],acc[kk][7]};
                    *(float4*)yp       = o0v;
                    *(float4*)(yp + 4) = o1v;
                    float ls = 0.f, lq = 0.f;
                    #pragma unroll
                    for (int i = 0; i < 8; i++) {
                        float v = acc[kk][i];
                        ls += v; lq = fmaf(v, v, lq);
                    }
                    s_acc[kk] += ls; q_acc[kk] += lq;
                }
            }
        }
    }

    // per-o reduction across the 16 lanes sharing the same row group (tx dim)
    #pragma unroll
    for (int kk = 0; kk < 4; kk++) {
        float s = s_acc[kk], q = q_acc[kk];
        #pragma unroll
        for (int d = 8; d >= 1; d >>= 1) {
            s += __shfl_xor_sync(0xffffffffu, s, d);
            q += __shfl_xor_sync(0xffffffffu, q, d);
        }
        int o = r0 + kk;
        if (tx == 0 && o < NN) {
            atomicAdd(&d_sum1[o], s);
            atomicAdd(&d_sq1[o], q);
        }
    }
}

// ---------------- K3: f = relu(bn1(Y)).reshape @ wf1^T + bf1, + bn2 stats ---
__global__ __launch_bounds__(256, 3)
void k3(const float* __restrict__ wf1, const float* __restrict__ bf1) {
    __shared__ float A_s[KT][68];   // z tile [k][m], pad 68 (16B-aligned rows)
    __shared__ float B_s[KT][68];   // wf1 tile [k][j]
    __shared__ float red0[H1D], red1[H1D];
    __shared__ float a1_s[NN], c1_s[NN];

    const int t = threadIdx.x;
    if (t < NN) { a1_s[t] = d_a1[t]; c1_s[t] = d_c1[t]; }

    const size_t b0 = (size_t)blockIdx.x * TBM;
    const int tx = t & 15, ty = t >> 4;
    const int lm = t >> 5, lk = t & 31;

    float acc[4][4] = {};
    const float* Yb = d_Y + b0 * FDIM;

    for (int k0 = 0; k0 < FDIM; k0 += KT) {
        __syncthreads();
        const int ki = k0 + lk;
        const int o = ki >> 7;
        const float a1v = a1_s[o], c1v = c1_s[o];
        #pragma unroll
        for (int s = 0; s < 8; s++) {
            int m = lm + s * 8;
            float v = Yb[(size_t)m * FDIM + ki];
            A_s[lk][m] = fmaxf(fmaf(a1v, v, c1v), 0.f);
            B_s[lk][m] = wf1[(size_t)m * FDIM + ki];
        }
        __syncthreads();
        #pragma unroll
        for (int k = 0; k < KT; k++) {
            float4 a4 = *(const float4*)&A_s[k][ty * 4];
            float4 b4 = *(const float4*)&B_s[k][tx * 4];
            float av[4] = {a4.x, a4.y, a4.z, a4.w};
            float bv[4] = {b4.x, b4.y, b4.z, b4.w};
            #pragma unroll
            for (int i = 0; i < 4; i++)
                #pragma unroll
                for (int j = 0; j < 4; j++)
                    acc[i][j] = fmaf(av[i], bv[j], acc[i][j]);
        }
    }

    float bfv[4];
    #pragma unroll
    for (int j = 0; j < 4; j++) bfv[j] = bf1[tx * 4 + j];

    float sj[4] = {0,0,0,0}, qj[4] = {0,0,0,0};
    #pragma unroll
    for (int i = 0; i < 4; i++) {
        float4 v;
        v.x = acc[i][0] + bfv[0];
        v.y = acc[i][1] + bfv[1];
        v.z = acc[i][2] + bfv[2];
        v.w = acc[i][3] + bfv[3];
        *(float4*)&d_f[(b0 + (size_t)ty * 4 + i) * H1D + tx * 4] = v;
        sj[0] += v.x; qj[0] = fmaf(v.x, v.x, qj[0]);
        sj[1] += v.y; qj[1] = fmaf(v.y, v.y, qj[1]);
        sj[2] += v.z; qj[2] = fmaf(v.z, v.z, qj[2]);
        sj[3] += v.w; qj[3] = fmaf(v.w, v.w, qj[3]);
    }

    if (t < H1D) { red0[t] = 0.f; red1[t] = 0.f; }
    __syncthreads();
    #pragma unroll
    for (int j = 0; j < 4; j++) {
        atomicAdd(&red0[tx * 4 + j], sj[j]);
        atomicAdd(&red1[tx * 4 + j], qj[j]);
    }
    __syncthreads();
    if (t < H1D) {
        atomicAdd(&d_sum2[t], red0[t]);
        atomicAdd(&d_sq2[t], red1[t]);
    }
}

// ---------------- K5: out = relu(bn2(f)) @ wf2^T + bf2 ----------------------
__global__ void k5(const float* __restrict__ wf2, const float* __restrict__ bf2,
                   float* __restrict__ out) {
    const int t = threadIdx.x;
    const int w = t >> 5, l = t & 31;
    const size_t b = (size_t)blockIdx.x * 8 + w;
    float f0 = d_f[b * H1D + l];
    float f1 = d_f[b * H1D + 32 + l];
    float z0 = fmaxf(fmaf(d_a2[l], f0, d_c2[l]), 0.f);
    float z1 = fmaxf(fmaf(d_a2[32 + l], f1, d_c2[32 + l]), 0.f);
    float p0 = fmaf(z0, wf2[l],      z1 * wf2[32 + l]);
    float p1 = fmaf(z0, wf2[64 + l], z1 * wf2[96 + l]);
    #pragma unroll
    for (int d = 16; d >= 1; d >>= 1) {
        p0 += __shfl_xor_sync(0xffffffffu, p0, d);
        p1 += __shfl_xor_sync(0xffffffffu, p1, d);
    }
    if (l == 0) {
        out[b * 2 + 0] = p0 + bf2[0];
        out[b * 2 + 1] = p1 + bf2[1];
    }
}

// ---------------- launch -----------------------------------------------------
extern "C" void kernel_launch(void* const* d_in, const int* in_sizes, int n_in,
                              void* d_out, int out_size) {
    const float* x   = (const float*)d_in[0];
    const float* w0  = (const float*)d_in[1];
    const float* b0  = (const float*)d_in[2];
    const float* w1  = (const float*)d_in[3];
    const float* b1  = (const float*)d_in[4];
    const float* wc  = (const float*)d_in[5];
    const float* bc  = (const float*)d_in[6];
    const float* g1  = (const float*)d_in[7];
    const float* be1 = (const float*)d_in[8];
    const float* wf1 = (const float*)d_in[9];
    const float* bf1 = (const float*)d_in[10];
    const float* g2  = (const float*)d_in[11];
    const float* be2 = (const float*)d_in[12];
    const float* wf2 = (const float*)d_in[13];
    const float* bf2 = (const float*)d_in[14];
    float* out = (float*)d_out;

    kinit<<<1, 128>>>();
    kprep<<<1, 128>>>(w0, b0, w1, b1);
    k1<<<B_N / SPB, 256>>>(x, wc, bc);
    k2<<<1, 64>>>(g1, be1);
    k3<<<B_N / TBM, 256>>>(wf1, bf1);
    k4<<<1, 64>>>(g2, be2);
    k5<<<B_N / 8, 256>>>(wf2, bf2, out);
}

// round 2
// speedup vs baseline: 1.0020x; 1.0020x over previous
#include <cuda_runtime.h>

#define B_N   32768
#define C_INN 14
#define NN    52      // nodes / conv channels
#define H1D   64
#define H2D   128
#define FDIM  (NN*H2D)  // 6656
#define EPSB  1e-5f
#define SPB   8       // samples per block in k1
#define KT    32      // k-tile in k3
#define TBM   64      // samples per block in k3

// ---------------- scratch (device globals; no allocations allowed) ----------
__device__ float d_W01[H2D * C_INN];                 // folded w1@w0  [128][14]
__device__ float d_b01[H2D];
__device__ float d_Y[(size_t)B_N * NN * H2D];        // 872 MB intermediate
__device__ float d_f[(size_t)B_N * H1D];             // fc1 output
__device__ float d_sum1[NN], d_sq1[NN];
__device__ float d_sum2[H1D], d_sq2[H1D];
__device__ float d_a1[NN], d_c1[NN];
__device__ float d_a2[H1D], d_c2[H1D];

// ---------------- tiny kernels ----------------------------------------------
__global__ void kinit() {
    int t = threadIdx.x;
    if (t < NN)  { d_sum1[t] = 0.f; d_sq1[t] = 0.f; }
    if (t < H1D) { d_sum2[t] = 0.f; d_sq2[t] = 0.f; }
}

// fold GAT+GCN weights: W01 = w1 @ w0  [128][14], b01 = w1@b0 + b1
__global__ void kprep(const float* __restrict__ w0, const float* __restrict__ b0,
                      const float* __restrict__ w1, const float* __restrict__ b1) {
    int l = threadIdx.x;           // 128 threads
    if (l >= H2D) return;
    float bb = b1[l];
    for (int m = 0; m < H1D; m++) bb = fmaf(w1[l*H1D + m], b0[m], bb);
    d_b01[l] = bb;
    for (int j = 0; j < C_INN; j++) {
        float s = 0.f;
        for (int m = 0; m < H1D; m++) s = fmaf(w1[l*H1D + m], w0[m*C_INN + j], s);
        d_W01[l*C_INN + j] = s;
    }
}

__global__ void k2(const float* __restrict__ g1, const float* __restrict__ be1) {
    int t = threadIdx.x;
    if (t < NN) {
        float inv = 1.f / ((float)B_N * (float)H2D);
        float mu  = d_sum1[t] * inv;
        float var = d_sq1[t] * inv - mu * mu;
        float a   = g1[t] * rsqrtf(var + EPSB);
        d_a1[t] = a; d_c1[t] = be1[t] - mu * a;
    }
}

__global__ void k4(const float* __restrict__ g2, const float* __restrict__ be2) {
    int t = threadIdx.x;
    if (t < H1D) {
        float inv = 1.f / (float)B_N;
        float mu  = d_sum2[t] * inv;
        float var = d_sq2[t] * inv - mu * mu;
        float a   = g2[t] * rsqrtf(var + EPSB);
        d_a2[t] = a; d_c2[t] = be2[t] - mu * a;
    }
}

// ---------------- K1: per-sample H = relu(X@W01^T+b01); Y = wc@H + bc -------
__global__ __launch_bounds__(256, 2)
void k1(const float* __restrict__ x, const float* __restrict__ wc,
        const float* __restrict__ bc) {
    __shared__ float wc_s[NN * NN];        // [o][c]  10816 B
    __shared__ float W01t_s[C_INN * H2D];  // [j][l]   7168 B
    __shared__ float b01_s[H2D];
    __shared__ float bc_s[NN];
    __shared__ float X_s[64 * C_INN];      // [node][j], rows 52..63 unused
    __shared__ float H_s[NN * H2D];        // [c][l]  26624 B

    const int t = threadIdx.x;

    for (int i = t; i < NN * NN; i += 256) wc_s[i] = wc[i];
    for (int i = t; i < H2D * C_INN; i += 256) {
        int l = i / C_INN, j = i - l * C_INN;
        W01t_s[j * H2D + l] = d_W01[i];
    }
    if (t < H2D) b01_s[t] = d_b01[t];
    if (t < NN)  bc_s[t]  = bc[t];

    const int tx = t & 15, ty = t >> 4;
    const int l0 = tx * 8;           // feature-column tile
    const int r0 = ty * 4;           // row tile (c for H stage, o for Y stage)

    float s_acc[4] = {0.f,0.f,0.f,0.f}, q_acc[4] = {0.f,0.f,0.f,0.f};

    const size_t base = (size_t)blockIdx.x * SPB;
    for (int sp = 0; sp < SPB; sp++) {
        const size_t b = base + sp;
        __syncthreads();  // previous sample's readers done
        // load X: x[b][j][n] -> X_s[n][j]
        const float* xb = x + b * (C_INN * NN);
        for (int i = t; i < C_INN * NN; i += 256) {
            int j = i / NN, n = i - j * NN;
            X_s[n * C_INN + j] = xb[i];
        }
        __syncthreads();

        // ---- H stage: H[c][l] = relu(sum_j X[c][j]*W01[l][j] + b01[l]) ----
        {
            float acc[4][8];
            float b01v[8];
            #pragma unroll
            for (int i = 0; i < 8; i++) b01v[i] = b01_s[l0 + i];
            #pragma unroll
            for (int a = 0; a < 4; a++)
                #pragma unroll
                for (int i = 0; i < 8; i++) acc[a][i] = b01v[i];
            #pragma unroll
            for (int j = 0; j < C_INN; j++) {
                float4 wA = *(const float4*)&W01t_s[j * H2D + l0];
                float4 wB = *(const float4*)&W01t_s[j * H2D + l0 + 4];
                float wv[8] = {wA.x,wA.y,wA.z,wA.w,wB.x,wB.y,wB.z,wB.w};
                #pragma unroll
                for (int a = 0; a < 4; a++) {
                    float xv = X_s[(r0 + a) * C_INN + j];
                    #pragma unroll
                    for (int i = 0; i < 8; i++) acc[a][i] = fmaf(xv, wv[i], acc[a][i]);
                }
            }
            #pragma unroll
            for (int a = 0; a < 4; a++) {
                int c = r0 + a;
                if (c < NN) {
                    float4 o0v, o1v;
                    o0v.x = fmaxf(acc[a][0], 0.f); o0v.y = fmaxf(acc[a][1], 0.f);
                    o0v.z = fmaxf(acc[a][2], 0.f); o0v.w = fmaxf(acc[a][3], 0.f);
                    o1v.x = fmaxf(acc[a][4], 0.f); o1v.y = fmaxf(acc[a][5], 0.f);
                    o1v.z = fmaxf(acc[a][6], 0.f); o1v.w = fmaxf(acc[a][7], 0.f);
                    *(float4*)&H_s[c * H2D + l0]     = o0v;
                    *(float4*)&H_s[c * H2D + l0 + 4] = o1v;
                }
            }
        }
        __syncthreads();

        // ---- Y stage: Y[o][l] = sum_c wc[o][c]*H[c][l] + bc[o] ----
        {
            float acc[4][8];
            const float* wrow[4];
            #pragma unroll
            for (int kk = 0; kk < 4; kk++) {
                int o = r0 + kk; if (o > NN - 1) o = NN - 1;  // clamp; discarded later
                wrow[kk] = &wc_s[o * NN];
                float bcv = bc_s[o];
                #pragma unroll
                for (int i = 0; i < 8; i++) acc[kk][i] = bcv;
            }
            #pragma unroll 4
            for (int c = 0; c < NN; c++) {
                float4 hA = *(const float4*)&H_s[c * H2D + l0];
                float4 hB = *(const float4*)&H_s[c * H2D + l0 + 4];
                float hv[8] = {hA.x,hA.y,hA.z,hA.w,hB.x,hB.y,hB.z,hB.w};
                #pragma unroll
                for (int kk = 0; kk < 4; kk++) {
                    float wv = wrow[kk][c];
                    #pragma unroll
                    for (int i = 0; i < 8; i++) acc[kk][i] = fmaf(wv, hv[i], acc[kk][i]);
                }
            }
            #pragma unroll
            for (int kk = 0; kk < 4; kk++) {
                int o = r0 + kk;
                if (o < NN) {
                    float* yp = d_Y + ((size_t)b * NN + o) * H2D + l0;
                    float4 o0v = {acc[kk][0],acc[kk][1],acc[kk][2],acc[kk][3]};
                    float4 o1v = {acc[kk][4],acc[kk][5],acc[kk][6],acc[kk][7]};
                    *(float4*)yp       = o0v;
                    *(float4*)(yp + 4) = o1v;
                    float ls = 0.f, lq = 0.f;
                    #pragma unroll
                    for (int i = 0; i < 8; i++) {
                        float v = acc[kk][i];
                        ls += v; lq = fmaf(v, v, lq);
                    }
                    s_acc[kk] += ls; q_acc[kk] += lq;
                }
            }
        }
    }

    // per-o reduction across the 16 lanes sharing the same row group (tx dim)
    #pragma unroll
    for (int kk = 0; kk < 4; kk++) {
        float s = s_acc[kk], q = q_acc[kk];
        #pragma unroll
        for (int d = 8; d >= 1; d >>= 1) {
            s += __shfl_xor_sync(0xffffffffu, s, d);
            q += __shfl_xor_sync(0xffffffffu, q, d);
        }
        int o = r0 + kk;
        if (tx == 0 && o < NN) {
            atomicAdd(&d_sum1[o], s);
            atomicAdd(&d_sq1[o], q);
        }
    }
}

// ---------------- K3: f = relu(bn1(Y)).reshape @ wf1^T + bf1, + bn2 stats ---
__global__ __launch_bounds__(256, 3)
void k3(const float* __restrict__ wf1, const float* __restrict__ bf1) {
    __shared__ float A_s[KT][68];   // z tile [k][m], pad 68 (16B-aligned rows)
    __shared__ float B_s[KT][68];   // wf1 tile [k][j]
    __shared__ float red0[H1D], red1[H1D];
    __shared__ float a1_s[NN], c1_s[NN];

    const int t = threadIdx.x;
    if (t < NN) { a1_s[t] = d_a1[t]; c1_s[t] = d_c1[t]; }

    const size_t b0 = (size_t)blockIdx.x * TBM;
    const int tx = t & 15, ty = t >> 4;
    const int lm = t >> 5, lk = t & 31;

    float acc[4][4] = {};
    const float* Yb = d_Y + b0 * FDIM;

    for (int k0 = 0; k0 < FDIM; k0 += KT) {
        __syncthreads();
        const int ki = k0 + lk;
        const int o = ki >> 7;
        const float a1v = a1_s[o], c1v = c1_s[o];
        #pragma unroll
        for (int s = 0; s < 8; s++) {
            int m = lm + s * 8;
            float v = Yb[(size_t)m * FDIM + ki];
            A_s[lk][m] = fmaxf(fmaf(a1v, v, c1v), 0.f);
            B_s[lk][m] = wf1[(size_t)m * FDIM + ki];
        }
        __syncthreads();
        #pragma unroll
        for (int k = 0; k < KT; k++) {
            float4 a4 = *(const float4*)&A_s[k][ty * 4];
            float4 b4 = *(const float4*)&B_s[k][tx * 4];
            float av[4] = {a4.x, a4.y, a4.z, a4.w};
            float bv[4] = {b4.x, b4.y, b4.z, b4.w};
            #pragma unroll
            for (int i = 0; i < 4; i++)
                #pragma unroll
                for (int j = 0; j < 4; j++)
                    acc[i][j] = fmaf(av[i], bv[j], acc[i][j]);
        }
    }

    float bfv[4];
    #pragma unroll
    for (int j = 0; j < 4; j++) bfv[j] = bf1[tx * 4 + j];

    float sj[4] = {0,0,0,0}, qj[4] = {0,0,0,0};
    #pragma unroll
    for (int i = 0; i < 4; i++) {
        float4 v;
        v.x = acc[i][0] + bfv[0];
        v.y = acc[i][1] + bfv[1];
        v.z = acc[i][2] + bfv[2];
        v.w = acc[i][3] + bfv[3];
        *(float4*)&d_f[(b0 + (size_t)ty * 4 + i) * H1D + tx * 4] = v;
        sj[0] += v.x; qj[0] = fmaf(v.x, v.x, qj[0]);
        sj[1] += v.y; qj[1] = fmaf(v.y, v.y, qj[1]);
        sj[2] += v.z; qj[2] = fmaf(v.z, v.z, qj[2]);
        sj[3] += v.w; qj[3] = fmaf(v.w, v.w, qj[3]);
    }

    if (t < H1D) { red0[t] = 0.f; red1[t] = 0.f; }
    __syncthreads();
    #pragma unroll
    for (int j = 0; j < 4; j++) {
        atomicAdd(&red0[tx * 4 + j], sj[j]);
        atomicAdd(&red1[tx * 4 + j], qj[j]);
    }
    __syncthreads();
    if (t < H1D) {
        atomicAdd(&d_sum2[t], red0[t]);
        atomicAdd(&d_sq2[t], red1[t]);
    }
}

// ---------------- K5: out = relu(bn2(f)) @ wf2^T + bf2 ----------------------
__global__ void k5(const float* __restrict__ wf2, const float* __restrict__ bf2,
                   float* __restrict__ out) {
    const int t = threadIdx.x;
    const int w = t >> 5, l = t & 31;
    const size_t b = (size_t)blockIdx.x * 8 + w;
    float f0 = d_f[b * H1D + l];
    float f1 = d_f[b * H1D + 32 + l];
    float z0 = fmaxf(fmaf(d_a2[l], f0, d_c2[l]), 0.f);
    float z1 = fmaxf(fmaf(d_a2[32 + l], f1, d_c2[32 + l]), 0.f);
    float p0 = fmaf(z0, wf2[l],      z1 * wf2[32 + l]);
    float p1 = fmaf(z0, wf2[64 + l], z1 * wf2[96 + l]);
    #pragma unroll
    for (int d = 16; d >= 1; d >>= 1) {
        p0 += __shfl_xor_sync(0xffffffffu, p0, d);
        p1 += __shfl_xor_sync(0xffffffffu, p1, d);
    }
    if (l == 0) {
        out[b * 2 + 0] = p0 + bf2[0];
        out[b * 2 + 1] = p1 + bf2[1];
    }
}

// ---------------- launch -----------------------------------------------------
extern "C" void kernel_launch(void* const* d_in, const int* in_sizes, int n_in,
                              void* d_out, int out_size) {
    const float* x   = (const float*)d_in[0];
    const float* w0  = (const float*)d_in[1];
    const float* b0  = (const float*)d_in[2];
    const float* w1  = (const float*)d_in[3];
    const float* b1  = (const float*)d_in[4];
    const float* wc  = (const float*)d_in[5];
    const float* bc  = (const float*)d_in[6];
    const float* g1  = (const float*)d_in[7];
    const float* be1 = (const float*)d_in[8];
    const float* wf1 = (const float*)d_in[9];
    const float* bf1 = (const float*)d_in[10];
    const float* g2  = (const float*)d_in[11];
    const float* be2 = (const float*)d_in[12];
    const float* wf2 = (const float*)d_in[13];
    const float* bf2 = (const float*)d_in[14];
    float* out = (float*)d_out;

    kinit<<<1, 128>>>();
    kprep<<<1, 128>>>(w0, b0, w1, b1);
    k1<<<B_N / SPB, 256>>>(x, wc, bc);
    k2<<<1, 64>>>(g1, be1);
    k3<<<B_N / TBM, 256>>>(wf1, bf1);
    k4<<<1, 64>>>(g2, be2);
    k5<<<B_N / 8, 256>>>(wf2, bf2, out);
}

// round 4
// speedup vs baseline: 1.3670x; 1.3642x over previous
#include <cuda_runtime.h>
#include <cstdint>

#define B_N   32768
#define C_INN 14
#define NN    52
#define H1D   64
#define H2D   128
#define FDIM  (NN*H2D)   // 6656
#define EPSB  1e-5f
#define SPB   8
#define NKT   (FDIM/32)  // 208 k-tiles of width 32

// ---------------- scratch ----------------------------------------------------
__device__ float d_W01[H2D * C_INN];
__device__ float d_b01[H2D];
__device__ float d_Y[(size_t)B_N * NN * H2D];
__device__ float d_f[(size_t)B_N * H1D];
__device__ float d_sum1[NN], d_sq1[NN];
__device__ float d_sum2[H1D], d_sq2[H1D];
__device__ float d_a1[NN], d_c1[NN];
__device__ float d_a2[H1D], d_c2[H1D];

#define TF32R(o, f) asm("cvt.rna.tf32.f32 %0, %1;" : "=r"(o) : "f"(f))

__device__ __forceinline__ void mma_tf32(float c[4],
                                         uint32_t a0, uint32_t a1, uint32_t a2, uint32_t a3,
                                         uint32_t b0, uint32_t b1) {
    asm volatile(
        "mma.sync.aligned.m16n8k8.row.col.f32.tf32.tf32.f32 "
        "{%0,%1,%2,%3}, {%4,%5,%6,%7}, {%8,%9}, {%0,%1,%2,%3};"
        : "+f"(c[0]), "+f"(c[1]), "+f"(c[2]), "+f"(c[3])
        : "r"(a0), "r"(a1), "r"(a2), "r"(a3), "r"(b0), "r"(b1));
}

// ---------------- tiny kernels -----------------------------------------------
__global__ void kinit() {
    int t = threadIdx.x;
    if (t < NN)  { d_sum1[t] = 0.f; d_sq1[t] = 0.f; }
    if (t < H1D) { d_sum2[t] = 0.f; d_sq2[t] = 0.f; }
}
__global__ void kprep(const float* __restrict__ w0, const float* __restrict__ b0,
                      const float* __restrict__ w1, const float* __restrict__ b1) {
    int l = threadIdx.x;
    if (l >= H2D) return;
    float bb = b1[l];
    for (int m = 0; m < H1D; m++) bb = fmaf(w1[l*H1D + m], b0[m], bb);
    d_b01[l] = bb;
    for (int j = 0; j < C_INN; j++) {
        float s = 0.f;
        for (int m = 0; m < H1D; m++) s = fmaf(w1[l*H1D + m], w0[m*C_INN + j], s);
        d_W01[l*C_INN + j] = s;
    }
}
__global__ void k2(const float* __restrict__ g1, const float* __restrict__ be1) {
    int t = threadIdx.x;
    if (t < NN) {
        float inv = 1.f / ((float)B_N * (float)H2D);
        float mu  = d_sum1[t] * inv;
        float var = d_sq1[t] * inv - mu * mu;
        float a   = g1[t] * rsqrtf(var + EPSB);
        d_a1[t] = a; d_c1[t] = be1[t] - mu * a;
    }
}
__global__ void k4(const float* __restrict__ g2, const float* __restrict__ be2) {
    int t = threadIdx.x;
    if (t < H1D) {
        float inv = 1.f / (float)B_N;
        float mu  = d_sum2[t] * inv;
        float var = d_sq2[t] * inv - mu * mu;
        float a   = g2[t] * rsqrtf(var + EPSB);
        d_a2[t] = a; d_c2[t] = be2[t] - mu * a;
    }
}

// ---------------- K1 (unchanged, known-passing) -------------------------------
__global__ __launch_bounds__(256, 2)
void k1(const float* __restrict__ x, const float* __restrict__ wc,
        const float* __restrict__ bc) {
    __shared__ float wc_s[NN * NN];
    __shared__ float W01t_s[C_INN * H2D];
    __shared__ float b01_s[H2D];
    __shared__ float bc_s[NN];
    __shared__ float X_s[64 * C_INN];
    __shared__ float H_s[NN * H2D];

    const int t = threadIdx.x;
    for (int i = t; i < NN * NN; i += 256) wc_s[i] = wc[i];
    for (int i = t; i < H2D * C_INN; i += 256) {
        int l = i / C_INN, j = i - l * C_INN;
        W01t_s[j * H2D + l] = d_W01[i];
    }
    if (t < H2D) b01_s[t] = d_b01[t];
    if (t < NN)  bc_s[t]  = bc[t];

    const int tx = t & 15, ty = t >> 4;
    const int l0 = tx * 8, r0 = ty * 4;
    float s_acc[4] = {0.f,0.f,0.f,0.f}, q_acc[4] = {0.f,0.f,0.f,0.f};

    const size_t base = (size_t)blockIdx.x * SPB;
    for (int sp = 0; sp < SPB; sp++) {
        const size_t b = base + sp;
        __syncthreads();
        const float* xb = x + b * (C_INN * NN);
        for (int i = t; i < C_INN * NN; i += 256) {
            int j = i / NN, n = i - j * NN;
            X_s[n * C_INN + j] = xb[i];
        }
        __syncthreads();
        {
            float acc[4][8];
            float b01v[8];
            #pragma unroll
            for (int i = 0; i < 8; i++) b01v[i] = b01_s[l0 + i];
            #pragma unroll
            for (int a = 0; a < 4; a++)
                #pragma unroll
                for (int i = 0; i < 8; i++) acc[a][i] = b01v[i];
            #pragma unroll
            for (int j = 0; j < C_INN; j++) {
                float4 wA = *(const float4*)&W01t_s[j * H2D + l0];
                float4 wB = *(const float4*)&W01t_s[j * H2D + l0 + 4];
                float wv[8] = {wA.x,wA.y,wA.z,wA.w,wB.x,wB.y,wB.z,wB.w};
                #pragma unroll
                for (int a = 0; a < 4; a++) {
                    float xv = X_s[(r0 + a) * C_INN + j];
                    #pragma unroll
                    for (int i = 0; i < 8; i++) acc[a][i] = fmaf(xv, wv[i], acc[a][i]);
                }
            }
            #pragma unroll
            for (int a = 0; a < 4; a++) {
                int c = r0 + a;
                if (c < NN) {
                    float4 o0v, o1v;
                    o0v.x = fmaxf(acc[a][0], 0.f); o0v.y = fmaxf(acc[a][1], 0.f);
                    o0v.z = fmaxf(acc[a][2], 0.f); o0v.w = fmaxf(acc[a][3], 0.f);
                    o1v.x = fmaxf(acc[a][4], 0.f); o1v.y = fmaxf(acc[a][5], 0.f);
                    o1v.z = fmaxf(acc[a][6], 0.f); o1v.w = fmaxf(acc[a][7], 0.f);
                    *(float4*)&H_s[c * H2D + l0]     = o0v;
                    *(float4*)&H_s[c * H2D + l0 + 4] = o1v;
                }
            }
        }
        __syncthreads();
        {
            float acc[4][8];
            const float* wrow[4];
            #pragma unroll
            for (int kk = 0; kk < 4; kk++) {
                int o = r0 + kk; if (o > NN - 1) o = NN - 1;
                wrow[kk] = &wc_s[o * NN];
                float bcv = bc_s[o];
                #pragma unroll
                for (int i = 0; i < 8; i++) acc[kk][i] = bcv;
            }
            #pragma unroll 4
            for (int c = 0; c < NN; c++) {
                float4 hA = *(const float4*)&H_s[c * H2D + l0];
                float4 hB = *(const float4*)&H_s[c * H2D + l0 + 4];
                float hv[8] = {hA.x,hA.y,hA.z,hA.w,hB.x,hB.y,hB.z,hB.w};
                #pragma unroll
                for (int kk = 0; kk < 4; kk++) {
                    float wv = wrow[kk][c];
                    #pragma unroll
                    for (int i = 0; i < 8; i++) acc[kk][i] = fmaf(wv, hv[i], acc[kk][i]);
                }
            }
            #pragma unroll
            for (int kk = 0; kk < 4; kk++) {
                int o = r0 + kk;
                if (o < NN) {
                    float* yp = d_Y + ((size_t)b * NN + o) * H2D + l0;
                    float4 o0v = {acc[kk][0],acc[kk][1],acc[kk][2],acc[kk][3]};
                    float4 o1v = {acc[kk][4],acc[kk][5],acc[kk][6],acc[kk][7]};
                    *(float4*)yp       = o0v;
                    *(float4*)(yp + 4) = o1v;
                    float ls = 0.f, lq = 0.f;
                    #pragma unroll
                    for (int i = 0; i < 8; i++) {
                        float v = acc[kk][i];
                        ls += v; lq = fmaf(v, v, lq);
                    }
                    s_acc[kk] += ls; q_acc[kk] += lq;
                }
            }
        }
    }
    #pragma unroll
    for (int kk = 0; kk < 4; kk++) {
        float s = s_acc[kk], q = q_acc[kk];
        #pragma unroll
        for (int d = 8; d >= 1; d >>= 1) {
            s += __shfl_xor_sync(0xffffffffu, s, d);
            q += __shfl_xor_sync(0xffffffffu, q, d);
        }
        int o = r0 + kk;
        if (tx == 0 && o < NN) {
            atomicAdd(&d_sum1[o], s);
            atomicAdd(&d_sq1[o], q);
        }
    }
}

// ---------------- K3: tf32 mma.sync GEMM, 128 samples x 64 out per block ------
// smem union: As[128][36] + Bs[64][36]  (27648 B)  vs  stage[128][65] (33280 B)
#define K3_SMEM_BYTES (128 * 65 * 4)

__global__ __launch_bounds__(256)
void k3mma(const float* __restrict__ wf1, const float* __restrict__ bf1) {
    __shared__ __align__(16) char smemraw[K3_SMEM_BYTES];
    float (*As)[36] = (float(*)[36])smemraw;
    float (*Bs)[36] = (float(*)[36])(smemraw + 128 * 36 * 4);
    float* stage = (float*)smemraw;
    __shared__ float a1_s[NN], c1_s[NN];

    const int t = threadIdx.x;
    const int w = t >> 5, lane = t & 31;
    const int gid = lane >> 2, tig = lane & 3;
    if (t < NN) { a1_s[t] = d_a1[t]; c1_s[t] = d_c1[t]; }
    __syncthreads();

    const size_t b0 = (size_t)blockIdx.x * 128;

    // producer mapping
    const int am = t >> 1, ah = t & 1;               // A: row am, cols [ah*16, ah*16+16)
    const float* Arow = d_Y + (b0 + am) * FDIM + ah * 16;
    const int bn = t >> 2, bq = t & 3;               // B: row bn, cols [bq*8, bq*8+8)
    const float* Brow = wf1 + (size_t)bn * FDIM + bq * 8;

    float acc[8][4];
    #pragma unroll
    for (int nt = 0; nt < 8; nt++)
        #pragma unroll
        for (int i = 0; i < 4; i++) acc[nt][i] = 0.f;

    // preload tile 0
    float4 aR[4], bR[2];
    #pragma unroll
    for (int i = 0; i < 4; i++) aR[i] = *(const float4*)(Arow + i * 4);
    #pragma unroll
    for (int i = 0; i < 2; i++) bR[i] = *(const float4*)(Brow + i * 4);

    const int arow_lo = w * 16 + gid;
    const int arow_hi = arow_lo + 8;

    for (int it = 0; it < NKT; it++) {
        const int k0 = it * 32;
        const int o = k0 >> 7;                 // constant within a 32-wide tile
        const float a1v = a1_s[o], c1v = c1_s[o];

        __syncthreads();   // previous tile's readers done -> smem writable
        // STS with bn1+relu+tf32 (A) and tf32 (B)
        #pragma unroll
        for (int i = 0; i < 4; i++) {
            float4 v = aR[i];
            uint32_t r0_, r1_, r2_, r3_;
            float e0 = fmaxf(fmaf(a1v, v.x, c1v), 0.f);
            float e1 = fmaxf(fmaf(a1v, v.y, c1v), 0.f);
            float e2 = fmaxf(fmaf(a1v, v.z, c1v), 0.f);
            float e3 = fmaxf(fmaf(a1v, v.w, c1v), 0.f);
            TF32R(r0_, e0); TF32R(r1_, e1); TF32R(r2_, e2); TF32R(r3_, e3);
            float4 sv = { __uint_as_float(r0_), __uint_as_float(r1_),
                          __uint_as_float(r2_), __uint_as_float(r3_) };
            *(float4*)&As[am][ah * 16 + i * 4] = sv;
        }
        #pragma unroll
        for (int i = 0; i < 2; i++) {
            float4 v = bR[i];
            uint32_t r0_, r1_, r2_, r3_;
            TF32R(r0_, v.x); TF32R(r1_, v.y); TF32R(r2_, v.z); TF32R(r3_, v.w);
            float4 sv = { __uint_as_float(r0_), __uint_as_float(r1_),
                          __uint_as_float(r2_), __uint_as_float(r3_) };
            *(float4*)&Bs[bn][bq * 8 + i * 4] = sv;
        }
        // prefetch next tile (overlaps with compute below)
        if (it + 1 < NKT) {
            const int kn = k0 + 32;
            #pragma unroll
            for (int i = 0; i < 4; i++) aR[i] = *(const float4*)(Arow + kn + i * 4);
            #pragma unroll
            for (int i = 0; i < 2; i++) bR[i] = *(const float4*)(Brow + kn + i * 4);
        }
        __syncthreads();   // tile ready

        // compute: 4 k-steps of 8, 8 n-tiles
        #pragma unroll
        for (int ks = 0; ks < 4; ks++) {
            const int kc = ks * 8 + tig;
            uint32_t a0 = __float_as_uint(As[arow_lo][kc]);
            uint32_t a1 = __float_as_uint(As[arow_hi][kc]);
            uint32_t a2 = __float_as_uint(As[arow_lo][kc + 4]);
            uint32_t a3 = __float_as_uint(As[arow_hi][kc + 4]);
            #pragma unroll
            for (int nt = 0; nt < 8; nt++) {
                const int brow = nt * 8 + gid;
                uint32_t bb0 = __float_as_uint(Bs[brow][kc]);
                uint32_t bb1 = __float_as_uint(Bs[brow][kc + 4]);
                mma_tf32(acc[nt], a0, a1, a2, a3, bb0, bb1);
            }
        }
    }

    __syncthreads();   // done reading As/Bs; stage aliases them

    // epilogue: +bf1, store d_f, stage for bn2 stats
    #pragma unroll
    for (int nt = 0; nt < 8; nt++) {
        const int n0 = nt * 8 + tig * 2;
        const float bf0 = __ldg(bf1 + n0), bf1v = __ldg(bf1 + n0 + 1);
        float v0 = acc[nt][0] + bf0, v1 = acc[nt][1] + bf1v;
        float v2 = acc[nt][2] + bf0, v3 = acc[nt][3] + bf1v;
        *(float2*)&d_f[(b0 + arow_lo) * H1D + n0] = make_float2(v0, v1);
        *(float2*)&d_f[(b0 + arow_hi) * H1D + n0] = make_float2(v2, v3);
        stage[arow_lo * 65 + n0]     = v0;
        stage[arow_lo * 65 + n0 + 1] = v1;
        stage[arow_hi * 65 + n0]     = v2;
        stage[arow_hi * 65 + n0 + 1] = v3;
    }
    __syncthreads();
    if (t < H1D) {
        float s = 0.f, q = 0.f;
        #pragma unroll 4
        for (int r = 0; r < 128; r++) {
            float v = stage[r * 65 + t];
            s += v; q = fmaf(v, v, q);
        }
        atomicAdd(&d_sum2[t], s);
        atomicAdd(&d_sq2[t], q);
    }
}

// ---------------- K5 ----------------------------------------------------------
__global__ void k5(const float* __restrict__ wf2, const float* __restrict__ bf2,
                   float* __restrict__ out) {
    const int t = threadIdx.x;
    const int w = t >> 5, l = t & 31;
    const size_t b = (size_t)blockIdx.x * 8 + w;
    float f0 = d_f[b * H1D + l];
    float f1 = d_f[b * H1D + 32 + l];
    float z0 = fmaxf(fmaf(d_a2[l], f0, d_c2[l]), 0.f);
    float z1 = fmaxf(fmaf(d_a2[32 + l], f1, d_c2[32 + l]), 0.f);
    float p0 = fmaf(z0, wf2[l],      z1 * wf2[32 + l]);
    float p1 = fmaf(z0, wf2[64 + l], z1 * wf2[96 + l]);
    #pragma unroll
    for (int d = 16; d >= 1; d >>= 1) {
        p0 += __shfl_xor_sync(0xffffffffu, p0, d);
        p1 += __shfl_xor_sync(0xffffffffu, p1, d);
    }
    if (l == 0) {
        out[b * 2 + 0] = p0 + bf2[0];
        out[b * 2 + 1] = p1 + bf2[1];
    }
}

// ---------------- launch -------------------------------------------------------
extern "C" void kernel_launch(void* const* d_in, const int* in_sizes, int n_in,
                              void* d_out, int out_size) {
    const float* x   = (const float*)d_in[0];
    const float* w0  = (const float*)d_in[1];
    const float* b0  = (const float*)d_in[2];
    const float* w1  = (const float*)d_in[3];
    const float* b1  = (const float*)d_in[4];
    const float* wc  = (const float*)d_in[5];
    const float* bc  = (const float*)d_in[6];
    const float* g1  = (const float*)d_in[7];
    const float* be1 = (const float*)d_in[8];
    const float* wf1 = (const float*)d_in[9];
    const float* bf1 = (const float*)d_in[10];
    const float* g2  = (const float*)d_in[11];
    const float* be2 = (const float*)d_in[12];
    const float* wf2 = (const float*)d_in[13];
    const float* bf2 = (const float*)d_in[14];
    float* out = (float*)d_out;

    kinit<<<1, 128>>>();
    kprep<<<1, 128>>>(w0, b0, w1, b1);
    k1<<<B_N / SPB, 256>>>(x, wc, bc);
    k2<<<1, 64>>>(g1, be1);
    k3mma<<<B_N / 128, 256>>>(wf1, bf1);
    k4<<<1, 64>>>(g2, be2);
    k5<<<B_N / 8, 256>>>(wf2, bf2, out);
}

// round 6
// speedup vs baseline: 2.1489x; 1.5720x over previous
#include <cuda_runtime.h>
#include <cstdint>

#define B_N   32768
#define C_INN 14
#define NN    52
#define H1D   64
#define H2D   128
#define FDIM  (NN*H2D)   // 6656
#define EPSB  1e-5f
#define SPB   8
#define NKT   (FDIM/32)  // 208 k-tiles for K3

// ---------------- scratch ----------------------------------------------------
__device__ float d_W01[H2D * C_INN];
__device__ float d_b01[H2D];
__device__ float d_Y[(size_t)B_N * NN * H2D];
__device__ float d_f[(size_t)B_N * H1D];
__device__ float d_sum1[NN], d_sq1[NN];
__device__ float d_sum2[H1D], d_sq2[H1D];
__device__ float d_a1[NN], d_c1[NN];
__device__ float d_a2[H1D], d_c2[H1D];

#define TF32R(o, f) asm("cvt.rna.tf32.f32 %0, %1;" : "=r"(o) : "f"(f))

__device__ __forceinline__ void mma_tf32(float c[4],
                                         uint32_t a0, uint32_t a1, uint32_t a2, uint32_t a3,
                                         uint32_t b0, uint32_t b1) {
    asm volatile(
        "mma.sync.aligned.m16n8k8.row.col.f32.tf32.tf32.f32 "
        "{%0,%1,%2,%3}, {%4,%5,%6,%7}, {%8,%9}, {%0,%1,%2,%3};"
        : "+f"(c[0]), "+f"(c[1]), "+f"(c[2]), "+f"(c[3])
        : "r"(a0), "r"(a1), "r"(a2), "r"(a3), "r"(b0), "r"(b1));
}

// ---------------- tiny kernels -----------------------------------------------
__global__ void kinit() {
    int t = threadIdx.x;
    if (t < NN)  { d_sum1[t] = 0.f; d_sq1[t] = 0.f; }
    if (t < H1D) { d_sum2[t] = 0.f; d_sq2[t] = 0.f; }
}
__global__ void kprep(const float* __restrict__ w0, const float* __restrict__ b0,
                      const float* __restrict__ w1, const float* __restrict__ b1) {
    int l = threadIdx.x;
    if (l >= H2D) return;
    float bb = b1[l];
    for (int m = 0; m < H1D; m++) bb = fmaf(w1[l*H1D + m], b0[m], bb);
    d_b01[l] = bb;
    for (int j = 0; j < C_INN; j++) {
        float s = 0.f;
        for (int m = 0; m < H1D; m++) s = fmaf(w1[l*H1D + m], w0[m*C_INN + j], s);
        d_W01[l*C_INN + j] = s;
    }
}
__global__ void k2(const float* __restrict__ g1, const float* __restrict__ be1) {
    int t = threadIdx.x;
    if (t < NN) {
        float inv = 1.f / ((float)B_N * (float)H2D);
        float mu  = d_sum1[t] * inv;
        float var = d_sq1[t] * inv - mu * mu;
        float a   = g1[t] * rsqrtf(var + EPSB);
        d_a1[t] = a; d_c1[t] = be1[t] - mu * a;
    }
}
__global__ void k4(const float* __restrict__ g2, const float* __restrict__ be2) {
    int t = threadIdx.x;
    if (t < H1D) {
        float inv = 1.f / (float)B_N;
        float mu  = d_sum2[t] * inv;
        float var = d_sq2[t] * inv - mu * mu;
        float a   = g2[t] * rsqrtf(var + EPSB);
        d_a2[t] = a; d_c2[t] = be2[t] - mu * a;
    }
}

// ---------------- K1: stage1 fp32 FFMA -> Ht; stage2 tf32 mma -> Y -----------
// dyn smem float offsets:
#define HT_OFF   0                       // Ht[128][72]  (36864B) | stage[64][132] alias
#define W01T_OFF (128*72)                // W01t[16][128]
#define WCP_OFF  (W01T_OFF + 16*128)     // wcp_r[64][68]
#define XT_OFF   (WCP_OFF + 64*68)       // Xt[16][68]
#define B01_OFF  (XT_OFF + 16*68)        // [128]
#define BC_OFF   (B01_OFF + 128)         // [64]
#define K1_SMEM_FLOATS (BC_OFF + 64)
#define K1_SMEM_BYTES  (K1_SMEM_FLOATS * 4)

__global__ __launch_bounds__(256)
void k1mma(const float* __restrict__ x, const float* __restrict__ wc,
           const float* __restrict__ bc) {
    extern __shared__ __align__(16) float sm[];
    const int t = threadIdx.x;
    const int w = t >> 5, lane = t & 31;
    const int gid = lane >> 2, tig = lane & 3;

    // ---- one-time fills ----
    // W01t[j][l] = d_W01[l][j]   (fp32, stage-1 operand)
    for (int i = t; i < H2D * C_INN; i += 256) {
        int l = i / C_INN, j = i - l * C_INN;
        sm[W01T_OFF + j * 128 + l] = d_W01[i];
    }
    for (int i = t; i < 16 * 128; i += 256) {
        int j = i >> 7;
        if (j >= C_INN) sm[W01T_OFF + i] = 0.f;   // pad rows 14,15
    }
    // wcp_r[o][kk]: permuted + tf32-rounded wc, zero pad  (stage-2 B operand)
    for (int i = t; i < 64 * 64; i += 256) {
        int o = i >> 6, kk = i & 63;
        int m = kk & 7;
        int src_c = (kk & ~7) + (m >> 1) + ((m & 1) << 2);
        float v = 0.f;
        if (o < NN && src_c < NN) v = wc[o * NN + src_c];
        uint32_t r; TF32R(r, v);
        sm[WCP_OFF + o * 68 + kk] = __uint_as_float(r);
    }
    // Xt zero-fill (per-sample fill only touches j<14, n<52)
    for (int i = t; i < 16 * 68; i += 256) sm[XT_OFF + i] = 0.f;
    if (t < H2D) sm[B01_OFF + t] = d_b01[t];
    if (t < 64)  sm[BC_OFF + t] = (t < NN) ? bc[t] : 0.f;
    __syncthreads();

    const int tx = t & 15, ty = t >> 4;     // stage-1 tile: l0=8ty, c0=4tx
    const int lr0 = w * 16 + gid, lr1 = lr0 + 8;   // stage-2 m rows

    float sqs[8], sqq[8];
    #pragma unroll
    for (int i = 0; i < 8; i++) { sqs[i] = 0.f; sqq[i] = 0.f; }

    const size_t base = (size_t)blockIdx.x * SPB;
    for (int sp = 0; sp < SPB; sp++) {
        const size_t b = base + sp;
        // ---- load X^T: Xt[j][n] = x[b][j][n] (coalesced) ----
        const float* xb = x + b * (C_INN * NN);
        for (int i = t; i < C_INN * NN; i += 256) {
            int j = i / NN, n = i - j * NN;
            sm[XT_OFF + j * 68 + n] = xb[i];
        }
        __syncthreads();   // Xt ready; also separates prev readout from Ht writes

        // ---- stage 1 (fp32): Ht[l][c] = relu(sum_j W01[l][j] X[c][j] + b01[l])
        {
            float acc1[8][4];
            #pragma unroll
            for (int i = 0; i < 8; i++)
                #pragma unroll
                for (int a = 0; a < 4; a++) acc1[i][a] = 0.f;
            #pragma unroll
            for (int j = 0; j < C_INN; j++) {
                float4 xv = *(const float4*)&sm[XT_OFF + j * 68 + tx * 4];
                float4 wA = *(const float4*)&sm[W01T_OFF + j * 128 + ty * 8];
                float4 wB = *(const float4*)&sm[W01T_OFF + j * 128 + ty * 8 + 4];
                float wv[8] = {wA.x,wA.y,wA.z,wA.w,wB.x,wB.y,wB.z,wB.w};
                #pragma unroll
                for (int i = 0; i < 8; i++) {
                    acc1[i][0] = fmaf(wv[i], xv.x, acc1[i][0]);
                    acc1[i][1] = fmaf(wv[i], xv.y, acc1[i][1]);
                    acc1[i][2] = fmaf(wv[i], xv.z, acc1[i][2]);
                    acc1[i][3] = fmaf(wv[i], xv.w, acc1[i][3]);
                }
            }
            #pragma unroll
            for (int i = 0; i < 8; i++) {
                int l = ty * 8 + i;
                float bias = sm[B01_OFF + l];
                uint32_t r0_, r1_, r2_, r3_;
                TF32R(r0_, fmaxf(acc1[i][0] + bias, 0.f));
                TF32R(r1_, fmaxf(acc1[i][1] + bias, 0.f));
                TF32R(r2_, fmaxf(acc1[i][2] + bias, 0.f));
                TF32R(r3_, fmaxf(acc1[i][3] + bias, 0.f));
                float4 h = { __uint_as_float(r0_), __uint_as_float(r1_),
                             __uint_as_float(r2_), __uint_as_float(r3_) };
                *(float4*)&sm[HT_OFF + l * 72 + tx * 4] = h;
            }
        }
        __syncthreads();   // Ht ready

        // ---- stage 2 (tf32 mma): Yt[l][o] = Ht[l][c] @ wc^T ----
        float acc2[8][4];
        #pragma unroll
        for (int nt = 0; nt < 8; nt++)
            #pragma unroll
            for (int a = 0; a < 4; a++) acc2[nt][a] = 0.f;
        #pragma unroll
        for (int ks = 0; ks < 8; ks++) {
            const int kc = ks * 8 + tig;
            uint32_t a0 = __float_as_uint(sm[HT_OFF + lr0 * 72 + kc]);
            uint32_t a1 = __float_as_uint(sm[HT_OFF + lr1 * 72 + kc]);
            uint32_t a2 = __float_as_uint(sm[HT_OFF + lr0 * 72 + kc + 4]);
            uint32_t a3 = __float_as_uint(sm[HT_OFF + lr1 * 72 + kc + 4]);
            #pragma unroll
            for (int nt = 0; nt < 8; nt++) {
                float2 bp = *(const float2*)&sm[WCP_OFF + (nt * 8 + gid) * 68 + ks * 8 + tig * 2];
                mma_tf32(acc2[nt], a0, a1, a2, a3,
                         __float_as_uint(bp.x), __float_as_uint(bp.y));
            }
        }
        __syncthreads();   // all Ht reads done before stage overwrite (alias)

        // ---- epilogue 2: +bc, transpose into stage[o][132] ----
        #pragma unroll
        for (int nt = 0; nt < 8; nt++) {
            int o0 = nt * 8 + tig * 2;
            float b0v = sm[BC_OFF + o0], b1v = sm[BC_OFF + o0 + 1];
            sm[HT_OFF + o0 * 132 + lr0]       = acc2[nt][0] + b0v;
            sm[HT_OFF + (o0 + 1) * 132 + lr0] = acc2[nt][1] + b1v;
            sm[HT_OFF + o0 * 132 + lr1]       = acc2[nt][2] + b0v;
            sm[HT_OFF + (o0 + 1) * 132 + lr1] = acc2[nt][3] + b1v;
        }
        __syncthreads();   // stage ready

        // ---- readout: coalesced Y store + bn1 partials ----
        float* yb = d_Y + b * FDIM;
        #pragma unroll
        for (int i = 0; i < 8; i++) {
            int o = w * 8 + i;
            if (o < NN) {
                float4 v = *(const float4*)&sm[HT_OFF + o * 132 + lane * 4];
                *(float4*)&yb[o * 128 + lane * 4] = v;
                sqs[i] += v.x + v.y + v.z + v.w;
                sqq[i] = fmaf(v.x, v.x, sqq[i]);
                sqq[i] = fmaf(v.y, v.y, sqq[i]);
                sqq[i] = fmaf(v.z, v.z, sqq[i]);
                sqq[i] = fmaf(v.w, v.w, sqq[i]);
            }
        }
        // loop back: Xt fill + sync separates this readout from next Ht writes
    }

    // ---- bn1 stats: warp-reduce, one atomic pair per o per block ----
    #pragma unroll
    for (int i = 0; i < 8; i++) {
        float s = sqs[i], q = sqq[i];
        #pragma unroll
        for (int d = 16; d >= 1; d >>= 1) {
            s += __shfl_xor_sync(0xffffffffu, s, d);
            q += __shfl_xor_sync(0xffffffffu, q, d);
        }
        int o = w * 8 + i;
        if (lane == 0 && o < NN) {
            atomicAdd(&d_sum1[o], s);
            atomicAdd(&d_sq1[o], q);
        }
    }
}

// ---------------- K3: tf32 mma.sync GEMM (UNCHANGED, known-passing) -----------
#define K3_SMEM_BYTES (128 * 65 * 4)

__global__ __launch_bounds__(256)
void k3mma(const float* __restrict__ wf1, const float* __restrict__ bf1) {
    __shared__ __align__(16) char smemraw[K3_SMEM_BYTES];
    float (*As)[36] = (float(*)[36])smemraw;
    float (*Bs)[36] = (float(*)[36])(smemraw + 128 * 36 * 4);
    float* stage = (float*)smemraw;
    __shared__ float a1_s[NN], c1_s[NN];

    const int t = threadIdx.x;
    const int w = t >> 5, lane = t & 31;
    const int gid = lane >> 2, tig = lane & 3;
    if (t < NN) { a1_s[t] = d_a1[t]; c1_s[t] = d_c1[t]; }
    __syncthreads();

    const size_t b0 = (size_t)blockIdx.x * 128;

    const int am = t >> 1, ah = t & 1;
    const float* Arow = d_Y + (b0 + am) * FDIM + ah * 16;
    const int bn = t >> 2, bq = t & 3;
    const float* Brow = wf1 + (size_t)bn * FDIM + bq * 8;

    float acc[8][4];
    #pragma unroll
    for (int nt = 0; nt < 8; nt++)
        #pragma unroll
        for (int i = 0; i < 4; i++) acc[nt][i] = 0.f;

    float4 aR[4], bR[2];
    #pragma unroll
    for (int i = 0; i < 4; i++) aR[i] = *(const float4*)(Arow + i * 4);
    #pragma unroll
    for (int i = 0; i < 2; i++) bR[i] = *(const float4*)(Brow + i * 4);

    const int arow_lo = w * 16 + gid;
    const int arow_hi = arow_lo + 8;

    for (int it = 0; it < NKT; it++) {
        const int k0 = it * 32;
        const int o = k0 >> 7;
        const float a1v = a1_s[o], c1v = c1_s[o];

        __syncthreads();
        #pragma unroll
        for (int i = 0; i < 4; i++) {
            float4 v = aR[i];
            uint32_t r0_, r1_, r2_, r3_;
            float e0 = fmaxf(fmaf(a1v, v.x, c1v), 0.f);
            float e1 = fmaxf(fmaf(a1v, v.y, c1v), 0.f);
            float e2 = fmaxf(fmaf(a1v, v.z, c1v), 0.f);
            float e3 = fmaxf(fmaf(a1v, v.w, c1v), 0.f);
            TF32R(r0_, e0); TF32R(r1_, e1); TF32R(r2_, e2); TF32R(r3_, e3);
            float4 sv = { __uint_as_float(r0_), __uint_as_float(r1_),
                          __uint_as_float(r2_), __uint_as_float(r3_) };
            *(float4*)&As[am][ah * 16 + i * 4] = sv;
        }
        #pragma unroll
        for (int i = 0; i < 2; i++) {
            float4 v = bR[i];
            uint32_t r0_, r1_, r2_, r3_;
            TF32R(r0_, v.x); TF32R(r1_, v.y); TF32R(r2_, v.z); TF32R(r3_, v.w);
            float4 sv = { __uint_as_float(r0_), __uint_as_float(r1_),
                          __uint_as_float(r2_), __uint_as_float(r3_) };
            *(float4*)&Bs[bn][bq * 8 + i * 4] = sv;
        }
        if (it + 1 < NKT) {
            const int kn = k0 + 32;
            #pragma unroll
            for (int i = 0; i < 4; i++) aR[i] = *(const float4*)(Arow + kn + i * 4);
            #pragma unroll
            for (int i = 0; i < 2; i++) bR[i] = *(const float4*)(Brow + kn + i * 4);
        }
        __syncthreads();

        #pragma unroll
        for (int ks = 0; ks < 4; ks++) {
            const int kc = ks * 8 + tig;
            uint32_t a0 = __float_as_uint(As[arow_lo][kc]);
            uint32_t a1 = __float_as_uint(As[arow_hi][kc]);
            uint32_t a2 = __float_as_uint(As[arow_lo][kc + 4]);
            uint32_t a3 = __float_as_uint(As[arow_hi][kc + 4]);
            #pragma unroll
            for (int nt = 0; nt < 8; nt++) {
                const int brow = nt * 8 + gid;
                uint32_t bb0 = __float_as_uint(Bs[brow][kc]);
                uint32_t bb1 = __float_as_uint(Bs[brow][kc + 4]);
                mma_tf32(acc[nt], a0, a1, a2, a3, bb0, bb1);
            }
        }
    }

    __syncthreads();

    #pragma unroll
    for (int nt = 0; nt < 8; nt++) {
        const int n0 = nt * 8 + tig * 2;
        const float bf0 = __ldg(bf1 + n0), bf1v = __ldg(bf1 + n0 + 1);
        float v0 = acc[nt][0] + bf0, v1 = acc[nt][1] + bf1v;
        float v2 = acc[nt][2] + bf0, v3 = acc[nt][3] + bf1v;
        *(float2*)&d_f[(b0 + arow_lo) * H1D + n0] = make_float2(v0, v1);
        *(float2*)&d_f[(b0 + arow_hi) * H1D + n0] = make_float2(v2, v3);
        stage[arow_lo * 65 + n0]     = v0;
        stage[arow_lo * 65 + n0 + 1] = v1;
        stage[arow_hi * 65 + n0]     = v2;
        stage[arow_hi * 65 + n0 + 1] = v3;
    }
    __syncthreads();
    if (t < H1D) {
        float s = 0.f, q = 0.f;
        #pragma unroll 4
        for (int r = 0; r < 128; r++) {
            float v = stage[r * 65 + t];
            s += v; q = fmaf(v, v, q);
        }
        atomicAdd(&d_sum2[t], s);
        atomicAdd(&d_sq2[t], q);
    }
}

// ---------------- K5 ----------------------------------------------------------
__global__ void k5(const float* __restrict__ wf2, const float* __restrict__ bf2,
                   float* __restrict__ out) {
    const int t = threadIdx.x;
    const int w = t >> 5, l = t & 31;
    const size_t b = (size_t)blockIdx.x * 8 + w;
    float f0 = d_f[b * H1D + l];
    float f1 = d_f[b * H1D + 32 + l];
    float z0 = fmaxf(fmaf(d_a2[l], f0, d_c2[l]), 0.f);
    float z1 = fmaxf(fmaf(d_a2[32 + l], f1, d_c2[32 + l]), 0.f);
    float p0 = fmaf(z0, wf2[l],      z1 * wf2[32 + l]);
    float p1 = fmaf(z0, wf2[64 + l], z1 * wf2[96 + l]);
    #pragma unroll
    for (int d = 16; d >= 1; d >>= 1) {
        p0 += __shfl_xor_sync(0xffffffffu, p0, d);
        p1 += __shfl_xor_sync(0xffffffffu, p1, d);
    }
    if (l == 0) {
        out[b * 2 + 0] = p0 + bf2[0];
        out[b * 2 + 1] = p1 + bf2[1];
    }
}

// ---------------- launch -------------------------------------------------------
extern "C" void kernel_launch(void* const* d_in, const int* in_sizes, int n_in,
                              void* d_out, int out_size) {
    const float* x   = (const float*)d_in[0];
    const float* w0  = (const float*)d_in[1];
    const float* b0  = (const float*)d_in[2];
    const float* w1  = (const float*)d_in[3];
    const float* b1  = (const float*)d_in[4];
    const float* wc  = (const float*)d_in[5];
    const float* bc  = (const float*)d_in[6];
    const float* g1  = (const float*)d_in[7];
    const float* be1 = (const float*)d_in[8];
    const float* wf1 = (const float*)d_in[9];
    const float* bf1 = (const float*)d_in[10];
    const float* g2  = (const float*)d_in[11];
    const float* be2 = (const float*)d_in[12];
    const float* wf2 = (const float*)d_in[13];
    const float* bf2 = (const float*)d_in[14];
    float* out = (float*)d_out;

    cudaFuncSetAttribute(k1mma, cudaFuncAttributeMaxDynamicSharedMemorySize, K1_SMEM_BYTES);

    kinit<<<1, 128>>>();
    kprep<<<1, 128>>>(w0, b0, w1, b1);
    k1mma<<<B_N / SPB, 256, K1_SMEM_BYTES>>>(x, wc, bc);
    k2<<<1, 64>>>(g1, be1);
    k3mma<<<B_N / 128, 256>>>(wf1, bf1);
    k4<<<1, 64>>>(g2, be2);
    k5<<<B_N / 8, 256>>>(wf2, bf2, out);
}